// round 1
// baseline (speedup 1.0000x reference)
#include <cuda_runtime.h>
#include <cuda_bf16.h>
#include <cstdint>

// Neural CYK parser. n=16 tokens, R=64 rules, V=26 vocab.
// chart[L][s][r] = max_{k,j,l} relu(W[r,j,l] * chart[k][s][j] * chart[L-k][s+k][l])
// Output: chart[16][0][0] (single float).
//
// Key identity used: for scalar W and candidates p_k,
//   max_k (W * p_k) = max(W * max_k p_k, W * min_k p_k)
// which collapses the k-split loop exactly.

#define NTOK 16
#define R 64
#define JL 4096              // 64*64
#define CHUNK 128            // jl elements per block
#define NCHUNK (JL / CHUNK)  // 32

// Scratch (allocation-free rule: static device globals).
__device__ float g_chart[17][NTOK][R];   // 17*16*64 floats
__device__ float g_Wt[JL * R];           // W transposed: Wt[jl*64 + r] = W[r,jl]

// ---------------------------------------------------------------------------
// Init: transpose W, zero chart (levels != 1), set chart[1][s] = E[tokens[s]].
// ---------------------------------------------------------------------------
__global__ void init_kernel(const int* __restrict__ tokens,
                            const float* __restrict__ W,
                            const float* __restrict__ E) {
    int idx = blockIdx.x * blockDim.x + threadIdx.x;   // 0 .. 262143

    // Transpose W (coalesced read, scattered write; 1MB, L2-trivial).
    if (idx < R * JL) {
        int r  = idx >> 12;        // idx / 4096
        int jl = idx & (JL - 1);
        g_Wt[jl * R + r] = W[idx];
    }

    // Zero chart everywhere except level 1.
    if (idx < 17 * NTOK * R) {
        int level = idx >> 10;     // /(16*64)
        if (level != 1) {
            (&g_chart[0][0][0])[idx] = 0.0f;
        }
    }

    // Level 1: chart[1][s][r] = E[tokens[s]][r].
    if (idx < NTOK * R) {
        int s = idx >> 6;
        int r = idx & 63;
        g_chart[1][s][r] = E[tokens[s] * R + r];
    }
}

// ---------------------------------------------------------------------------
// One CYK level. grid = (S cells, NCHUNK jl-chunks), block = 256 threads.
// ---------------------------------------------------------------------------
__global__ void __launch_bounds__(256, 8) level_kernel(int L) {
    const int s = blockIdx.x;        // cell start, 0..S-1
    const int c = blockIdx.y;        // jl chunk
    const int t = threadIdx.x;       // 0..255
    const int nk = L - 1;

    __shared__ float sU[15][R];      // chart[k][s],     k = 1..L-1
    __shared__ float sV[15][R];      // chart[L-k][s+k]
    __shared__ float sPmax[CHUNK];
    __shared__ float sPmin[CHUNK];
    __shared__ float sRed[4][R];

    // Stage the 2*(L-1) chart vectors this cell needs.
    for (int i = t; i < nk * R; i += 256) {
        int k = (i >> 6) + 1;
        int r = i & 63;
        sU[k - 1][r] = g_chart[k][s][r];
        sV[k - 1][r] = g_chart[L - k][s + k][r];
    }
    __syncthreads();

    // p-stats: pmax/pmin over k of u_k[j]*v_k[l] for this chunk's jl values.
    if (t < CHUNK) {
        int jl = c * CHUNK + t;
        int j = jl >> 6;
        int l = jl & 63;
        float pmx = -3.402823466e38f;
        float pmn =  3.402823466e38f;
        #pragma unroll 4
        for (int k = 0; k < nk; k++) {
            float p = sU[k][j] * sV[k][l];
            pmx = fmaxf(pmx, p);
            pmn = fminf(pmn, p);
        }
        sPmax[t] = pmx;
        sPmin[t] = pmn;
    }
    __syncthreads();

    // Main: thread (q, r) scans 32 jl rows of Wt; best = max over jl of
    // max(W*pmax, W*pmin), floored at 0 (relu).
    const int r = t & 63;
    const int q = t >> 6;            // 0..3, 32 jl each
    float best = 0.0f;
    const float* wt = g_Wt + (size_t)(c * CHUNK + q * 32) * R + r;
    #pragma unroll 8
    for (int i = 0; i < 32; i++) {
        float w  = wt[(size_t)i * R];          // coalesced across r
        int jl   = q * 32 + i;                 // local index into sPmax/sPmin
        float m  = fmaxf(w * sPmax[jl], w * sPmin[jl]);
        best = fmaxf(best, m);
    }
    sRed[q][r] = best;
    __syncthreads();

    // Combine 4 quarters, atomic-max into the chart cell (values >= 0 so
    // int-bit compare == float compare; chart pre-zeroed).
    if (t < R) {
        float b = fmaxf(fmaxf(sRed[0][t], sRed[1][t]),
                        fmaxf(sRed[2][t], sRed[3][t]));
        atomicMax((int*)&g_chart[L][s][t], __float_as_int(b));
    }
}

// ---------------------------------------------------------------------------
// Emit the single scalar output.
// ---------------------------------------------------------------------------
__global__ void final_kernel(float* __restrict__ out) {
    out[0] = g_chart[NTOK][0][0];
}

// ---------------------------------------------------------------------------
extern "C" void kernel_launch(void* const* d_in, const int* in_sizes, int n_in,
                              void* d_out, int out_size) {
    const int*   tokens = (const int*)d_in[0];
    const float* W      = (const float*)d_in[1];
    const float* E      = (const float*)d_in[2];
    float*       out    = (float*)d_out;

    // 262144 threads: transpose + zero + level-1 in one launch.
    init_kernel<<<1024, 256>>>(tokens, W, E);

    for (int L = 2; L <= NTOK; L++) {
        dim3 grid(NTOK - L + 1, NCHUNK);
        level_kernel<<<grid, 256>>>(L);
    }

    final_kernel<<<1, 1>>>(out);
}